// round 7
// baseline (speedup 1.0000x reference)
#include <cuda_runtime.h>
#include <math.h>
#include <stdint.h>

// Problem constants
#define B_   4
#define T_   2048
#define D_   1024
#define H_   16
#define DH_  64
#define NTOK (B_ * T_)     // 8192
#define E3   (3 * D_)      // 3072

// Scratch (device globals: allocation-free rule)
__device__ __align__(16) float g_qkv[NTOK * E3];   // [8192, 3072]
__device__ __align__(16) float g_att[NTOK * D_];   // [8192, 1024]
__device__ __align__(16) float g_xr [NTOK * D_];   // tf32-rounded x
__device__ __align__(16) float g_war[E3 * D_];     // tf32-rounded w_attn
__device__ __align__(16) float g_wpr[D_ * D_];     // tf32-rounded w_proj

// ---------------------------------------------------------------------------
// Helpers
// ---------------------------------------------------------------------------
__device__ __forceinline__ float tf32r(float x) {
    uint32_t u;
    asm("cvt.rna.tf32.f32 %0, %1;" : "=r"(u) : "f"(x));
    return __uint_as_float(u);
}

__device__ __forceinline__ void mma_tf32(float* c, const float* a, float b0, float b1) {
    asm volatile(
        "mma.sync.aligned.m16n8k8.row.col.f32.tf32.tf32.f32 "
        "{%0,%1,%2,%3}, {%4,%5,%6,%7}, {%8,%9}, {%0,%1,%2,%3};\n"
        : "+f"(c[0]), "+f"(c[1]), "+f"(c[2]), "+f"(c[3])
        : "r"(__float_as_uint(a[0])), "r"(__float_as_uint(a[1])),
          "r"(__float_as_uint(a[2])), "r"(__float_as_uint(a[3])),
          "r"(__float_as_uint(b0)), "r"(__float_as_uint(b1)));
}

__device__ __forceinline__ void cp_async16(void* smem_dst, const void* gsrc) {
    uint32_t s = (uint32_t)__cvta_generic_to_shared(smem_dst);
    asm volatile("cp.async.cg.shared.global [%0], [%1], 16;\n" :: "r"(s), "l"(gsrc) : "memory");
}
__device__ __forceinline__ void cp_commit() {
    asm volatile("cp.async.commit_group;\n" ::: "memory");
}
template<int N>
__device__ __forceinline__ void cp_wait() {
    asm volatile("cp.async.wait_group %0;\n" :: "n"(N) : "memory");
}

// ---------------------------------------------------------------------------
// Pre-round to tf32 (rna), elementwise
// ---------------------------------------------------------------------------
__global__ void round_tf32_kernel(const float4* __restrict__ in,
                                  float4* __restrict__ out, int n4)
{
    int i = blockIdx.x * blockDim.x + threadIdx.x;
    if (i < n4) {
        float4 v = in[i];
        v.x = tf32r(v.x); v.y = tf32r(v.y); v.z = tf32r(v.z); v.w = tf32r(v.w);
        out[i] = v;
    }
}

// ---------------------------------------------------------------------------
// TF32 NT GEMM, inputs pre-rounded. BM=BN=128, BK=32, 2-stage cp.async
// double buffer. 256 threads (8 warps), warp tile 64x32 via mma.m16n8k8.
// ---------------------------------------------------------------------------
#define BM 128
#define BN 128
#define BK 32
#define TSTR 36                                   // 32 + 4 pad words
#define GEMM_STAGE_WORDS (BM * TSTR)              // 4608 words per tile
#define GEMM_SMEM_BYTES (2 * 2 * GEMM_STAGE_WORDS * 4)   // 73728

__global__ void __launch_bounds__(256, 2)
gemm_nt_tf32(const float* __restrict__ A, const float* __restrict__ Bm,
             float* __restrict__ C, int M, int N, int K)
{
    extern __shared__ float smg[];
    const int SW = GEMM_STAGE_WORDS;

    const int tid  = threadIdx.x;
    const int lane = tid & 31;
    const int warp = tid >> 5;
    const int wm   = (warp >> 2) * 64;
    const int wn   = (warp & 3) * 32;
    const int m0   = blockIdx.y * BM;
    const int n0   = blockIdx.x * BN;

    float acc[4][4][4] = {};

    const int nIter = K / BK;   // 32

    auto issue = [&](int it, int s) {
        float* As = smg + s * 2 * SW;
        float* Bs = As + SW;
        int k0 = it * BK;
        #pragma unroll
        for (int i = 0; i < 4; ++i) {
            int c   = tid + i * 256;          // 0..1023 float4 chunks
            int row = c >> 3;                 // 8 float4 per row (32 floats)
            int lk  = (c & 7) << 2;
            cp_async16(&As[row * TSTR + lk], &A[(size_t)(m0 + row) * K + k0 + lk]);
            cp_async16(&Bs[row * TSTR + lk], &Bm[(size_t)(n0 + row) * K + k0 + lk]);
        }
        cp_commit();
    };

    issue(0, 0);
    issue(1, 1);

    for (int it = 0; it < nIter; ++it) {
        int s = it & 1;
        cp_wait<1>();
        __syncthreads();

        const float* As = smg + s * 2 * SW;
        const float* Bs = As + SW;

        #pragma unroll
        for (int ks = 0; ks < BK; ks += 8) {
            float af[4][4], bf[4][2];
            const int kk = ks + (lane & 3);
            #pragma unroll
            for (int mi = 0; mi < 4; ++mi) {
                int row = wm + mi * 16 + (lane >> 2);
                af[mi][0] = As[row * TSTR + kk];
                af[mi][1] = As[(row + 8) * TSTR + kk];
                af[mi][2] = As[row * TSTR + kk + 4];
                af[mi][3] = As[(row + 8) * TSTR + kk + 4];
            }
            #pragma unroll
            for (int nj = 0; nj < 4; ++nj) {
                int col = wn + nj * 8 + (lane >> 2);
                bf[nj][0] = Bs[col * TSTR + kk];
                bf[nj][1] = Bs[col * TSTR + kk + 4];
            }
            #pragma unroll
            for (int mi = 0; mi < 4; ++mi)
                #pragma unroll
                for (int nj = 0; nj < 4; ++nj)
                    mma_tf32(acc[mi][nj], af[mi], bf[nj][0], bf[nj][1]);
        }
        __syncthreads();
        if (it + 2 < nIter) issue(it + 2, s);
        else cp_commit();   // keep group accounting uniform
    }

    #pragma unroll
    for (int mi = 0; mi < 4; ++mi) {
        int row = m0 + wm + mi * 16 + (lane >> 2);
        #pragma unroll
        for (int nj = 0; nj < 4; ++nj) {
            int col = n0 + wn + nj * 8 + ((lane & 3) << 1);
            *(float2*)&C[(size_t)row * N + col] =
                make_float2(acc[mi][nj][0], acc[mi][nj][1]);
            *(float2*)&C[(size_t)(row + 8) * N + col] =
                make_float2(acc[mi][nj][2], acc[mi][nj][3]);
        }
    }
}

// ---------------------------------------------------------------------------
// Flash attention on tensor cores (single tf32 mma for S, fp32 softmax).
// BLOCK_M=64 q rows, key tiles of 64, DH=64. 128 threads (4 warps),
// each warp owns 16 q rows. S-frags + O-acc in registers.
// ---------------------------------------------------------------------------
#define AT_STR 68
#define ATTN_SMEM_BYTES (4 * 64 * AT_STR * 4)   // 69632

__global__ void __launch_bounds__(128, 3)
attn_mma_kernel(const float* __restrict__ qkv, float* __restrict__ out)
{
    extern __shared__ float sm[];
    float* Qb = sm;                  // [row][d]   q, scaled + rna
    float* Kb = Qb + 64 * AT_STR;    // [key][d]   rna
    float* Vt = Kb + 64 * AT_STR;    // [d][key]   rna
    float* Ps = Vt + 64 * AT_STR;    // [row][key] rna

    const int tid  = threadIdx.x;
    const int lane = tid & 31;
    const int warp = tid >> 5;
    const int g    = lane >> 2;      // 0..7
    const int t    = lane & 3;       // 0..3
    const int m0   = warp * 16;
    const int qt   = gridDim.x - 1 - blockIdx.x;   // big tiles first
    const int h    = blockIdx.y;
    const int b    = blockIdx.z;

    const float scale = 0.125f;
    const float* qbase = qkv + (size_t)(b * T_ + qt * 64) * E3 + h * DH_;

    // Load Q, pre-scale, round to tf32
    #pragma unroll
    for (int i = 0; i < 8; ++i) {
        int f = tid + i * 128;
        int row = f >> 4, c4 = (f & 15) << 2;
        float4 v = *(const float4*)(qbase + (size_t)row * E3 + c4);
        v.x = tf32r(v.x * scale); v.y = tf32r(v.y * scale);
        v.z = tf32r(v.z * scale); v.w = tf32r(v.w * scale);
        *(float4*)&Qb[row * AT_STR + c4] = v;
    }

    float pacc[8][4] = {};
    float m0r = -3.0e38f, m1r = -3.0e38f;
    float l0 = 0.0f, l1 = 0.0f;

    for (int n = 0; n <= qt; ++n) {
        __syncthreads();   // all PV/S reads of prev K,V done

        // Load K (rna) and V (rna, transposed)
        const float* kbase = qkv + (size_t)(b * T_ + n * 64) * E3 + D_ + h * DH_;
        #pragma unroll
        for (int i = 0; i < 8; ++i) {
            int f = tid + i * 128;
            int row = f >> 4, c4 = (f & 15) << 2;
            const float* kp = kbase + (size_t)row * E3 + c4;
            float4 kv = *(const float4*)kp;
            float4 vv = *(const float4*)(kp + D_);
            kv.x = tf32r(kv.x); kv.y = tf32r(kv.y);
            kv.z = tf32r(kv.z); kv.w = tf32r(kv.w);
            *(float4*)&Kb[row * AT_STR + c4] = kv;
            Vt[(c4 + 0) * AT_STR + row] = tf32r(vv.x);
            Vt[(c4 + 1) * AT_STR + row] = tf32r(vv.y);
            Vt[(c4 + 2) * AT_STR + row] = tf32r(vv.z);
            Vt[(c4 + 3) * AT_STR + row] = tf32r(vv.w);
        }
        __syncthreads();

        // S = Q @ K^T
        float sacc[8][4] = {};
        #pragma unroll
        for (int ks = 0; ks < 64; ks += 8) {
            float ab[4];
            int aoff = (m0 + g) * AT_STR + ks + t;
            ab[0] = Qb[aoff];     ab[1] = Qb[aoff + 8 * AT_STR];
            ab[2] = Qb[aoff + 4]; ab[3] = Qb[aoff + 8 * AT_STR + 4];
            #pragma unroll
            for (int j = 0; j < 8; ++j) {
                int boff = (j * 8 + g) * AT_STR + ks + t;
                mma_tf32(sacc[j], ab, Kb[boff], Kb[boff + 4]);
            }
        }

        // Causal mask on diagonal tile
        if (n == qt) {
            #pragma unroll
            for (int j = 0; j < 8; ++j) {
                int c0 = j * 8 + 2 * t, c1 = c0 + 1;
                int r0 = m0 + g, r1 = r0 + 8;
                if (c0 > r0) sacc[j][0] = -3.0e38f;
                if (c1 > r0) sacc[j][1] = -3.0e38f;
                if (c0 > r1) sacc[j][2] = -3.0e38f;
                if (c1 > r1) sacc[j][3] = -3.0e38f;
            }
        }

        // Online softmax (register frags, quad shuffles)
        float mx0 = -3.0e38f, mx1 = -3.0e38f;
        #pragma unroll
        for (int j = 0; j < 8; ++j) {
            mx0 = fmaxf(mx0, fmaxf(sacc[j][0], sacc[j][1]));
            mx1 = fmaxf(mx1, fmaxf(sacc[j][2], sacc[j][3]));
        }
        mx0 = fmaxf(mx0, __shfl_xor_sync(0xffffffffu, mx0, 1));
        mx0 = fmaxf(mx0, __shfl_xor_sync(0xffffffffu, mx0, 2));
        mx1 = fmaxf(mx1, __shfl_xor_sync(0xffffffffu, mx1, 1));
        mx1 = fmaxf(mx1, __shfl_xor_sync(0xffffffffu, mx1, 2));

        float mn0 = fmaxf(m0r, mx0);
        float mn1 = fmaxf(m1r, mx1);
        float cr0 = __expf(m0r - mn0);
        float cr1 = __expf(m1r - mn1);
        m0r = mn0; m1r = mn1;

        float rs0 = 0.0f, rs1 = 0.0f;
        #pragma unroll
        for (int j = 0; j < 8; ++j) {
            float p0 = __expf(sacc[j][0] - mn0);
            float p1 = __expf(sacc[j][1] - mn0);
            float p2 = __expf(sacc[j][2] - mn1);
            float p3 = __expf(sacc[j][3] - mn1);
            rs0 += p0 + p1; rs1 += p2 + p3;
            int prow0 = (m0 + g) * AT_STR + j * 8 + 2 * t;
            *(float2*)&Ps[prow0]              = make_float2(tf32r(p0), tf32r(p1));
            *(float2*)&Ps[prow0 + 8 * AT_STR] = make_float2(tf32r(p2), tf32r(p3));
        }
        rs0 += __shfl_xor_sync(0xffffffffu, rs0, 1);
        rs0 += __shfl_xor_sync(0xffffffffu, rs0, 2);
        rs1 += __shfl_xor_sync(0xffffffffu, rs1, 1);
        rs1 += __shfl_xor_sync(0xffffffffu, rs1, 2);
        l0 = l0 * cr0 + rs0;
        l1 = l1 * cr1 + rs1;

        #pragma unroll
        for (int j = 0; j < 8; ++j) {
            pacc[j][0] *= cr0; pacc[j][1] *= cr0;
            pacc[j][2] *= cr1; pacc[j][3] *= cr1;
        }
        __syncwarp();   // P visible within warp (rows are warp-private)

        // O += P @ V
        #pragma unroll
        for (int ks = 0; ks < 64; ks += 8) {
            float pf[4];
            int poff = (m0 + g) * AT_STR + ks + t;
            pf[0] = Ps[poff];     pf[1] = Ps[poff + 8 * AT_STR];
            pf[2] = Ps[poff + 4]; pf[3] = Ps[poff + 8 * AT_STR + 4];
            #pragma unroll
            for (int j = 0; j < 8; ++j) {
                int voff = (j * 8 + g) * AT_STR + ks + t;
                mma_tf32(pacc[j], pf, Vt[voff], Vt[voff + 4]);
            }
        }
    }

    // Epilogue: normalize, rna-round (proj GEMM consumes raw), store
    float linv0 = 1.0f / l0, linv1 = 1.0f / l1;
    float* obase = out + (size_t)(b * T_ + qt * 64) * D_ + h * DH_;
    #pragma unroll
    for (int j = 0; j < 8; ++j) {
        *(float2*)(obase + (size_t)(m0 + g) * D_ + j * 8 + 2 * t) =
            make_float2(tf32r(pacc[j][0] * linv0), tf32r(pacc[j][1] * linv0));
        *(float2*)(obase + (size_t)(m0 + g + 8) * D_ + j * 8 + 2 * t) =
            make_float2(tf32r(pacc[j][2] * linv1), tf32r(pacc[j][3] * linv1));
    }
}

// ---------------------------------------------------------------------------
extern "C" void kernel_launch(void* const* d_in, const int* in_sizes, int n_in,
                              void* d_out, int out_size)
{
    const float* x      = (const float*)d_in[0];
    const float* w_attn = (const float*)d_in[1];
    const float* w_proj = (const float*)d_in[2];
    float* out = (float*)d_out;

    float *qkv, *att, *xr, *war, *wpr;
    cudaGetSymbolAddress((void**)&qkv, g_qkv);
    cudaGetSymbolAddress((void**)&att, g_att);
    cudaGetSymbolAddress((void**)&xr,  g_xr);
    cudaGetSymbolAddress((void**)&war, g_war);
    cudaGetSymbolAddress((void**)&wpr, g_wpr);

    cudaFuncSetAttribute(gemm_nt_tf32,
                         cudaFuncAttributeMaxDynamicSharedMemorySize, GEMM_SMEM_BYTES);
    cudaFuncSetAttribute(attn_mma_kernel,
                         cudaFuncAttributeMaxDynamicSharedMemorySize, ATTN_SMEM_BYTES);

    // 0) Pre-round inputs to tf32 (rna) so GEMMs can cp.async raw
    {
        int n4x = NTOK * D_ / 4, n4a = E3 * D_ / 4, n4p = D_ * D_ / 4;
        round_tf32_kernel<<<(n4x + 255) / 256, 256>>>((const float4*)x, (float4*)xr, n4x);
        round_tf32_kernel<<<(n4a + 255) / 256, 256>>>((const float4*)w_attn, (float4*)war, n4a);
        round_tf32_kernel<<<(n4p + 255) / 256, 256>>>((const float4*)w_proj, (float4*)wpr, n4p);
    }

    // 1) QKV projection
    {
        dim3 grid(E3 / BN, NTOK / BM);
        gemm_nt_tf32<<<grid, 256, GEMM_SMEM_BYTES>>>(xr, war, qkv, NTOK, E3, D_);
    }

    // 2) Causal flash attention (tensor cores)
    {
        dim3 grid(T_ / 64, H_, B_);
        attn_mma_kernel<<<grid, 128, ATTN_SMEM_BYTES>>>(qkv, att);
    }

    // 3) Output projection
    {
        dim3 grid(D_ / BN, NTOK / BM);
        gemm_nt_tf32<<<grid, 256, GEMM_SMEM_BYTES>>>(att, wpr, out, NTOK, D_, D_);
    }
}

// round 8
// speedup vs baseline: 1.0606x; 1.0606x over previous
#include <cuda_runtime.h>
#include <math.h>
#include <stdint.h>

// Problem constants
#define B_   4
#define T_   2048
#define D_   1024
#define H_   16
#define DH_  64
#define NTOK (B_ * T_)     // 8192
#define E3   (3 * D_)      // 3072

// Scratch (device globals: allocation-free rule)
__device__ __align__(16) float g_qkv[NTOK * E3];   // [8192, 3072]
__device__ __align__(16) float g_att[NTOK * D_];   // [8192, 1024]
__device__ __align__(16) float g_xr [NTOK * D_];   // tf32-rounded x
__device__ __align__(16) float g_war[E3 * D_];     // tf32-rounded w_attn
__device__ __align__(16) float g_wpr[D_ * D_];     // tf32-rounded w_proj

// ---------------------------------------------------------------------------
// Helpers
// ---------------------------------------------------------------------------
__device__ __forceinline__ float tf32r(float x) {
    uint32_t u;
    asm("cvt.rna.tf32.f32 %0, %1;" : "=r"(u) : "f"(x));
    return __uint_as_float(u);
}

__device__ __forceinline__ void mma_tf32(float* c, const float* a, float b0, float b1) {
    asm volatile(
        "mma.sync.aligned.m16n8k8.row.col.f32.tf32.tf32.f32 "
        "{%0,%1,%2,%3}, {%4,%5,%6,%7}, {%8,%9}, {%0,%1,%2,%3};\n"
        : "+f"(c[0]), "+f"(c[1]), "+f"(c[2]), "+f"(c[3])
        : "r"(__float_as_uint(a[0])), "r"(__float_as_uint(a[1])),
          "r"(__float_as_uint(a[2])), "r"(__float_as_uint(a[3])),
          "r"(__float_as_uint(b0)), "r"(__float_as_uint(b1)));
}

__device__ __forceinline__ void cp_async16(void* smem_dst, const void* gsrc) {
    uint32_t s = (uint32_t)__cvta_generic_to_shared(smem_dst);
    asm volatile("cp.async.cg.shared.global [%0], [%1], 16;\n" :: "r"(s), "l"(gsrc) : "memory");
}
__device__ __forceinline__ void cp_commit() {
    asm volatile("cp.async.commit_group;\n" ::: "memory");
}
template<int N>
__device__ __forceinline__ void cp_wait() {
    asm volatile("cp.async.wait_group %0;\n" :: "n"(N) : "memory");
}

// ---------------------------------------------------------------------------
// Pre-round to tf32 (rna), elementwise
// ---------------------------------------------------------------------------
__global__ void round_tf32_kernel(const float4* __restrict__ in,
                                  float4* __restrict__ out, int n4)
{
    int i = blockIdx.x * blockDim.x + threadIdx.x;
    if (i < n4) {
        float4 v = in[i];
        v.x = tf32r(v.x); v.y = tf32r(v.y); v.z = tf32r(v.z); v.w = tf32r(v.w);
        out[i] = v;
    }
}

// ---------------------------------------------------------------------------
// TF32 NT GEMM, inputs pre-rounded. BM=BN=128, BK=32, 2-stage cp.async
// double buffer. 256 threads (8 warps), warp tile 64x32 via mma.m16n8k8.
// ---------------------------------------------------------------------------
#define BM 128
#define BN 128
#define BK 32
#define TSTR 36                                   // 32 + 4 pad words
#define GEMM_STAGE_WORDS (BM * TSTR)              // 4608 words per tile
#define GEMM_SMEM_BYTES (2 * 2 * GEMM_STAGE_WORDS * 4)   // 73728

__global__ void __launch_bounds__(256, 2)
gemm_nt_tf32(const float* __restrict__ A, const float* __restrict__ Bm,
             float* __restrict__ C, int M, int N, int K)
{
    extern __shared__ float smg[];
    const int SW = GEMM_STAGE_WORDS;

    const int tid  = threadIdx.x;
    const int lane = tid & 31;
    const int warp = tid >> 5;
    const int wm   = (warp >> 2) * 64;
    const int wn   = (warp & 3) * 32;
    const int m0   = blockIdx.y * BM;
    const int n0   = blockIdx.x * BN;

    float acc[4][4][4] = {};

    const int nIter = K / BK;   // 32

    auto issue = [&](int it, int s) {
        float* As = smg + s * 2 * SW;
        float* Bs = As + SW;
        int k0 = it * BK;
        #pragma unroll
        for (int i = 0; i < 4; ++i) {
            int c   = tid + i * 256;
            int row = c >> 3;
            int lk  = (c & 7) << 2;
            cp_async16(&As[row * TSTR + lk], &A[(size_t)(m0 + row) * K + k0 + lk]);
            cp_async16(&Bs[row * TSTR + lk], &Bm[(size_t)(n0 + row) * K + k0 + lk]);
        }
        cp_commit();
    };

    issue(0, 0);
    issue(1, 1);

    for (int it = 0; it < nIter; ++it) {
        int s = it & 1;
        cp_wait<1>();
        __syncthreads();

        const float* As = smg + s * 2 * SW;
        const float* Bs = As + SW;

        #pragma unroll
        for (int ks = 0; ks < BK; ks += 8) {
            float af[4][4], bf[4][2];
            const int kk = ks + (lane & 3);
            #pragma unroll
            for (int mi = 0; mi < 4; ++mi) {
                int row = wm + mi * 16 + (lane >> 2);
                af[mi][0] = As[row * TSTR + kk];
                af[mi][1] = As[(row + 8) * TSTR + kk];
                af[mi][2] = As[row * TSTR + kk + 4];
                af[mi][3] = As[(row + 8) * TSTR + kk + 4];
            }
            #pragma unroll
            for (int nj = 0; nj < 4; ++nj) {
                int col = wn + nj * 8 + (lane >> 2);
                bf[nj][0] = Bs[col * TSTR + kk];
                bf[nj][1] = Bs[col * TSTR + kk + 4];
            }
            #pragma unroll
            for (int mi = 0; mi < 4; ++mi)
                #pragma unroll
                for (int nj = 0; nj < 4; ++nj)
                    mma_tf32(acc[mi][nj], af[mi], bf[nj][0], bf[nj][1]);
        }
        __syncthreads();
        if (it + 2 < nIter) issue(it + 2, s);
        else cp_commit();   // keep group accounting uniform
    }

    #pragma unroll
    for (int mi = 0; mi < 4; ++mi) {
        int row = m0 + wm + mi * 16 + (lane >> 2);
        #pragma unroll
        for (int nj = 0; nj < 4; ++nj) {
            int col = n0 + wn + nj * 8 + ((lane & 3) << 1);
            *(float2*)&C[(size_t)row * N + col] =
                make_float2(acc[mi][nj][0], acc[mi][nj][1]);
            *(float2*)&C[(size_t)(row + 8) * N + col] =
                make_float2(acc[mi][nj][2], acc[mi][nj][3]);
        }
    }
}

// ---------------------------------------------------------------------------
// Flash attention on tensor cores. BLOCK_M=128 q rows (8 warps x 16 rows),
// key tiles of 64, DH=64, 256 threads. V kept in natural [key][d] layout
// (no transpose; conflict-free STS.128 and conflict-free B-fragment LDS).
// ---------------------------------------------------------------------------
#define ATM 128
#define AT_STR 68
// Qb[128][68] + Kb[64][68] + Vs[64][68] + Ps[128][68]
#define ATTN_SMEM_BYTES ((ATM + 64 + 64 + ATM) * AT_STR * 4)   // 104448

__global__ void __launch_bounds__(256, 2)
attn_mma_kernel(const float* __restrict__ qkv, float* __restrict__ out)
{
    extern __shared__ float sm[];
    float* Qb = sm;                   // [row][d]   q, scaled + rna
    float* Kb = Qb + ATM * AT_STR;    // [key][d]   rna
    float* Vs = Kb + 64 * AT_STR;     // [key][d]   rna (natural layout)
    float* Ps = Vs + 64 * AT_STR;     // [row][key] rna

    const int tid  = threadIdx.x;
    const int lane = tid & 31;
    const int warp = tid >> 5;        // 0..7
    const int g    = lane >> 2;       // 0..7
    const int t    = lane & 3;        // 0..3
    const int m0   = warp * 16;
    const int qt   = gridDim.x - 1 - blockIdx.x;   // big tiles first
    const int h    = blockIdx.y;
    const int b    = blockIdx.z;

    const float scale = 0.125f;
    const float* qbase = qkv + (size_t)(b * T_ + qt * ATM) * E3 + h * DH_;

    // Load Q tile (128 rows), pre-scale, round to tf32
    #pragma unroll
    for (int i = 0; i < 8; ++i) {
        int f = tid + i * 256;
        int row = f >> 4, c4 = (f & 15) << 2;
        float4 v = *(const float4*)(qbase + (size_t)row * E3 + c4);
        v.x = tf32r(v.x * scale); v.y = tf32r(v.y * scale);
        v.z = tf32r(v.z * scale); v.w = tf32r(v.w * scale);
        *(float4*)&Qb[row * AT_STR + c4] = v;
    }

    float pacc[8][4] = {};
    float m0r = -3.0e38f, m1r = -3.0e38f;
    float l0 = 0.0f, l1 = 0.0f;

    const int nTiles = 2 * qt + 2;    // 64-key tiles covering causal span

    for (int n = 0; n < nTiles; ++n) {
        __syncthreads();   // all PV/S reads of prev K,V done

        // Load K and V tiles (64 keys), rounded, natural [key][d] layout
        const float* kbase = qkv + (size_t)(b * T_ + n * 64) * E3 + D_ + h * DH_;
        #pragma unroll
        for (int i = 0; i < 4; ++i) {
            int f = tid + i * 256;
            int row = f >> 4, c4 = (f & 15) << 2;
            const float* kp = kbase + (size_t)row * E3 + c4;
            float4 kv = *(const float4*)kp;
            float4 vv = *(const float4*)(kp + D_);
            kv.x = tf32r(kv.x); kv.y = tf32r(kv.y);
            kv.z = tf32r(kv.z); kv.w = tf32r(kv.w);
            vv.x = tf32r(vv.x); vv.y = tf32r(vv.y);
            vv.z = tf32r(vv.z); vv.w = tf32r(vv.w);
            *(float4*)&Kb[row * AT_STR + c4] = kv;
            *(float4*)&Vs[row * AT_STR + c4] = vv;
        }
        __syncthreads();

        // S = Q @ K^T   (rows m0..m0+15 of this block)
        float sacc[8][4] = {};
        #pragma unroll
        for (int ks = 0; ks < 64; ks += 8) {
            float ab[4];
            int aoff = (m0 + g) * AT_STR + ks + t;
            ab[0] = Qb[aoff];     ab[1] = Qb[aoff + 8 * AT_STR];
            ab[2] = Qb[aoff + 4]; ab[3] = Qb[aoff + 8 * AT_STR + 4];
            #pragma unroll
            for (int j = 0; j < 8; ++j) {
                int boff = (j * 8 + g) * AT_STR + ks + t;
                mma_tf32(sacc[j], ab, Kb[boff], Kb[boff + 4]);
            }
        }

        // Causal mask on tiles crossing the diagonal (global indices)
        if (n >= 2 * qt) {
            int rg0 = qt * ATM + m0 + g;
            int rg1 = rg0 + 8;
            #pragma unroll
            for (int j = 0; j < 8; ++j) {
                int c0 = n * 64 + j * 8 + 2 * t, c1 = c0 + 1;
                if (c0 > rg0) sacc[j][0] = -3.0e38f;
                if (c1 > rg0) sacc[j][1] = -3.0e38f;
                if (c0 > rg1) sacc[j][2] = -3.0e38f;
                if (c1 > rg1) sacc[j][3] = -3.0e38f;
            }
        }

        // Online softmax (register frags, quad shuffles)
        float mx0 = -3.0e38f, mx1 = -3.0e38f;
        #pragma unroll
        for (int j = 0; j < 8; ++j) {
            mx0 = fmaxf(mx0, fmaxf(sacc[j][0], sacc[j][1]));
            mx1 = fmaxf(mx1, fmaxf(sacc[j][2], sacc[j][3]));
        }
        mx0 = fmaxf(mx0, __shfl_xor_sync(0xffffffffu, mx0, 1));
        mx0 = fmaxf(mx0, __shfl_xor_sync(0xffffffffu, mx0, 2));
        mx1 = fmaxf(mx1, __shfl_xor_sync(0xffffffffu, mx1, 1));
        mx1 = fmaxf(mx1, __shfl_xor_sync(0xffffffffu, mx1, 2));

        float mn0 = fmaxf(m0r, mx0);
        float mn1 = fmaxf(m1r, mx1);
        float cr0 = __expf(m0r - mn0);
        float cr1 = __expf(m1r - mn1);
        m0r = mn0; m1r = mn1;

        float rs0 = 0.0f, rs1 = 0.0f;
        #pragma unroll
        for (int j = 0; j < 8; ++j) {
            float p0 = __expf(sacc[j][0] - mn0);
            float p1 = __expf(sacc[j][1] - mn0);
            float p2 = __expf(sacc[j][2] - mn1);
            float p3 = __expf(sacc[j][3] - mn1);
            rs0 += p0 + p1; rs1 += p2 + p3;
            int prow0 = (m0 + g) * AT_STR + j * 8 + 2 * t;
            *(float2*)&Ps[prow0]              = make_float2(tf32r(p0), tf32r(p1));
            *(float2*)&Ps[prow0 + 8 * AT_STR] = make_float2(tf32r(p2), tf32r(p3));
        }
        rs0 += __shfl_xor_sync(0xffffffffu, rs0, 1);
        rs0 += __shfl_xor_sync(0xffffffffu, rs0, 2);
        rs1 += __shfl_xor_sync(0xffffffffu, rs1, 1);
        rs1 += __shfl_xor_sync(0xffffffffu, rs1, 2);
        l0 = l0 * cr0 + rs0;
        l1 = l1 * cr1 + rs1;

        #pragma unroll
        for (int j = 0; j < 8; ++j) {
            pacc[j][0] *= cr0; pacc[j][1] *= cr0;
            pacc[j][2] *= cr1; pacc[j][3] *= cr1;
        }
        __syncwarp();   // P visible within warp (rows are warp-private)

        // O += P @ V   (B fragment read directly from natural V layout)
        #pragma unroll
        for (int ks = 0; ks < 64; ks += 8) {
            float pf[4];
            int poff = (m0 + g) * AT_STR + ks + t;
            pf[0] = Ps[poff];     pf[1] = Ps[poff + 8 * AT_STR];
            pf[2] = Ps[poff + 4]; pf[3] = Ps[poff + 8 * AT_STR + 4];
            #pragma unroll
            for (int j = 0; j < 8; ++j) {
                float b0 = Vs[(ks + t) * AT_STR + j * 8 + g];
                float b1 = Vs[(ks + t + 4) * AT_STR + j * 8 + g];
                mma_tf32(pacc[j], pf, b0, b1);
            }
        }
    }

    // Epilogue: normalize, rna-round (proj GEMM consumes raw), store
    float linv0 = 1.0f / l0, linv1 = 1.0f / l1;
    float* obase = out + (size_t)(b * T_ + qt * ATM) * D_ + h * DH_;
    #pragma unroll
    for (int j = 0; j < 8; ++j) {
        *(float2*)(obase + (size_t)(m0 + g) * D_ + j * 8 + 2 * t) =
            make_float2(tf32r(pacc[j][0] * linv0), tf32r(pacc[j][1] * linv0));
        *(float2*)(obase + (size_t)(m0 + g + 8) * D_ + j * 8 + 2 * t) =
            make_float2(tf32r(pacc[j][2] * linv1), tf32r(pacc[j][3] * linv1));
    }
}

// ---------------------------------------------------------------------------
extern "C" void kernel_launch(void* const* d_in, const int* in_sizes, int n_in,
                              void* d_out, int out_size)
{
    const float* x      = (const float*)d_in[0];
    const float* w_attn = (const float*)d_in[1];
    const float* w_proj = (const float*)d_in[2];
    float* out = (float*)d_out;

    float *qkv, *att, *xr, *war, *wpr;
    cudaGetSymbolAddress((void**)&qkv, g_qkv);
    cudaGetSymbolAddress((void**)&att, g_att);
    cudaGetSymbolAddress((void**)&xr,  g_xr);
    cudaGetSymbolAddress((void**)&war, g_war);
    cudaGetSymbolAddress((void**)&wpr, g_wpr);

    cudaFuncSetAttribute(gemm_nt_tf32,
                         cudaFuncAttributeMaxDynamicSharedMemorySize, GEMM_SMEM_BYTES);
    cudaFuncSetAttribute(attn_mma_kernel,
                         cudaFuncAttributeMaxDynamicSharedMemorySize, ATTN_SMEM_BYTES);

    // 0) Pre-round inputs to tf32 (rna) so GEMMs can cp.async raw
    {
        int n4x = NTOK * D_ / 4, n4a = E3 * D_ / 4, n4p = D_ * D_ / 4;
        round_tf32_kernel<<<(n4x + 255) / 256, 256>>>((const float4*)x, (float4*)xr, n4x);
        round_tf32_kernel<<<(n4a + 255) / 256, 256>>>((const float4*)w_attn, (float4*)war, n4a);
        round_tf32_kernel<<<(n4p + 255) / 256, 256>>>((const float4*)w_proj, (float4*)wpr, n4p);
    }

    // 1) QKV projection
    {
        dim3 grid(E3 / BN, NTOK / BM);
        gemm_nt_tf32<<<grid, 256, GEMM_SMEM_BYTES>>>(xr, war, qkv, NTOK, E3, D_);
    }

    // 2) Causal flash attention (tensor cores)
    {
        dim3 grid(T_ / ATM, H_, B_);
        attn_mma_kernel<<<grid, 256, ATTN_SMEM_BYTES>>>(qkv, att);
    }

    // 3) Output projection
    {
        dim3 grid(D_ / BN, NTOK / BM);
        gemm_nt_tf32<<<grid, 256, GEMM_SMEM_BYTES>>>(att, wpr, out, NTOK, D_, D_);
    }
}

// round 11
// speedup vs baseline: 1.1786x; 1.1112x over previous
#include <cuda_runtime.h>
#include <math.h>
#include <stdint.h>

// Problem constants
#define B_   4
#define T_   2048
#define D_   1024
#define H_   16
#define DH_  64
#define NTOK (B_ * T_)     // 8192
#define E3   (3 * D_)      // 3072

// softmax scale folded with log2(e): logits come out in base-2 units
#define QSCALE 0.18033688011112042f   // 0.125 * log2(e)

// Scratch (device globals: allocation-free rule)
__device__ __align__(16) float g_qkv[NTOK * E3];   // [8192, 3072] (pre-rounded, Q pre-scaled)
__device__ __align__(16) float g_att[NTOK * D_];   // [8192, 1024] (pre-rounded)
__device__ __align__(16) float g_xr [NTOK * D_];   // tf32-rounded x
__device__ __align__(16) float g_war[E3 * D_];     // tf32-rounded w_attn
__device__ __align__(16) float g_wpr[D_ * D_];     // tf32-rounded w_proj

// ---------------------------------------------------------------------------
// Helpers
// ---------------------------------------------------------------------------
__device__ __forceinline__ float tf32r(float x) {
    uint32_t u;
    asm("cvt.rna.tf32.f32 %0, %1;" : "=r"(u) : "f"(x));
    return __uint_as_float(u);
}

__device__ __forceinline__ float ex2f(float x) {
    float r;
    asm("ex2.approx.ftz.f32 %0, %1;" : "=f"(r) : "f"(x));
    return r;
}

__device__ __forceinline__ void mma_tf32(float* c, const float* a, float b0, float b1) {
    asm volatile(
        "mma.sync.aligned.m16n8k8.row.col.f32.tf32.tf32.f32 "
        "{%0,%1,%2,%3}, {%4,%5,%6,%7}, {%8,%9}, {%0,%1,%2,%3};\n"
        : "+f"(c[0]), "+f"(c[1]), "+f"(c[2]), "+f"(c[3])
        : "r"(__float_as_uint(a[0])), "r"(__float_as_uint(a[1])),
          "r"(__float_as_uint(a[2])), "r"(__float_as_uint(a[3])),
          "r"(__float_as_uint(b0)), "r"(__float_as_uint(b1)));
}

__device__ __forceinline__ void cp_async16(void* smem_dst, const void* gsrc) {
    uint32_t s = (uint32_t)__cvta_generic_to_shared(smem_dst);
    asm volatile("cp.async.cg.shared.global [%0], [%1], 16;\n" :: "r"(s), "l"(gsrc) : "memory");
}
__device__ __forceinline__ void cp_commit() {
    asm volatile("cp.async.commit_group;\n" ::: "memory");
}
template<int N>
__device__ __forceinline__ void cp_wait() {
    asm volatile("cp.async.wait_group %0;\n" :: "n"(N) : "memory");
}

// ---------------------------------------------------------------------------
// Pre-round to tf32 (rna), elementwise
// ---------------------------------------------------------------------------
__global__ void round_tf32_kernel(const float4* __restrict__ in,
                                  float4* __restrict__ out, int n4)
{
    int i = blockIdx.x * blockDim.x + threadIdx.x;
    if (i < n4) {
        float4 v = in[i];
        v.x = tf32r(v.x); v.y = tf32r(v.y); v.z = tf32r(v.z); v.w = tf32r(v.w);
        out[i] = v;
    }
}

// ---------------------------------------------------------------------------
// TF32 NT GEMM, inputs pre-rounded. BM=BN=128, BK=32, 2-stage cp.async
// double buffer. 256 threads (8 warps), warp tile 64x32 via mma.m16n8k8.
// qkv_mode=1: epilogue rounds to tf32; Q columns (n0 < D_) also scaled by
// QSCALE first. qkv_mode=0: plain f32 store (final output).
// ---------------------------------------------------------------------------
#define BM 128
#define BN 128
#define BK 32
#define TSTR 36                                   // 32 + 4 pad words
#define GEMM_STAGE_WORDS (BM * TSTR)              // 4608 words per tile
#define GEMM_SMEM_BYTES (2 * 2 * GEMM_STAGE_WORDS * 4)   // 73728

__global__ void __launch_bounds__(256, 2)
gemm_nt_tf32(const float* __restrict__ A, const float* __restrict__ Bm,
             float* __restrict__ C, int M, int N, int K, int qkv_mode)
{
    extern __shared__ float smg[];
    const int SW = GEMM_STAGE_WORDS;

    const int tid  = threadIdx.x;
    const int lane = tid & 31;
    const int warp = tid >> 5;
    const int wm   = (warp >> 2) * 64;
    const int wn   = (warp & 3) * 32;
    const int m0   = blockIdx.y * BM;
    const int n0   = blockIdx.x * BN;

    float acc[4][4][4] = {};

    const int nIter = K / BK;

    auto issue = [&](int it, int s) {
        float* As = smg + s * 2 * SW;
        float* Bs = As + SW;
        int k0 = it * BK;
        #pragma unroll
        for (int i = 0; i < 4; ++i) {
            int c   = tid + i * 256;
            int row = c >> 3;
            int lk  = (c & 7) << 2;
            cp_async16(&As[row * TSTR + lk], &A[(size_t)(m0 + row) * K + k0 + lk]);
            cp_async16(&Bs[row * TSTR + lk], &Bm[(size_t)(n0 + row) * K + k0 + lk]);
        }
        cp_commit();
    };

    issue(0, 0);
    issue(1, 1);

    for (int it = 0; it < nIter; ++it) {
        int s = it & 1;
        cp_wait<1>();
        __syncthreads();

        const float* As = smg + s * 2 * SW;
        const float* Bs = As + SW;

        #pragma unroll
        for (int ks = 0; ks < BK; ks += 8) {
            float af[4][4], bf[4][2];
            const int kk = ks + (lane & 3);
            #pragma unroll
            for (int mi = 0; mi < 4; ++mi) {
                int row = wm + mi * 16 + (lane >> 2);
                af[mi][0] = As[row * TSTR + kk];
                af[mi][1] = As[(row + 8) * TSTR + kk];
                af[mi][2] = As[row * TSTR + kk + 4];
                af[mi][3] = As[(row + 8) * TSTR + kk + 4];
            }
            #pragma unroll
            for (int nj = 0; nj < 4; ++nj) {
                int col = wn + nj * 8 + (lane >> 2);
                bf[nj][0] = Bs[col * TSTR + kk];
                bf[nj][1] = Bs[col * TSTR + kk + 4];
            }
            #pragma unroll
            for (int mi = 0; mi < 4; ++mi)
                #pragma unroll
                for (int nj = 0; nj < 4; ++nj)
                    mma_tf32(acc[mi][nj], af[mi], bf[nj][0], bf[nj][1]);
        }
        __syncthreads();
        if (it + 2 < nIter) issue(it + 2, s);
        else cp_commit();   // keep group accounting uniform
    }

    const bool doRound = (qkv_mode != 0);
    const float esc = (doRound && n0 < D_) ? QSCALE : 1.0f;

    #pragma unroll
    for (int mi = 0; mi < 4; ++mi) {
        int row = m0 + wm + mi * 16 + (lane >> 2);
        #pragma unroll
        for (int nj = 0; nj < 4; ++nj) {
            int col = n0 + wn + nj * 8 + ((lane & 3) << 1);
            float2 v0 = make_float2(acc[mi][nj][0] * esc, acc[mi][nj][1] * esc);
            float2 v1 = make_float2(acc[mi][nj][2] * esc, acc[mi][nj][3] * esc);
            if (doRound) {
                v0.x = tf32r(v0.x); v0.y = tf32r(v0.y);
                v1.x = tf32r(v1.x); v1.y = tf32r(v1.y);
            }
            *(float2*)&C[(size_t)row * N + col]       = v0;
            *(float2*)&C[(size_t)(row + 8) * N + col] = v1;
        }
    }
}

// ---------------------------------------------------------------------------
// Flash attention on tensor cores. BLOCK_M=128 q rows (8 warps x 16 rows),
// key tiles of 64, DH=64, 256 threads. K/V double-buffered via cp.async
// (qkv is pre-rounded / pre-scaled by the GEMM epilogue). P stays in
// registers: S-accumulator fragments are permuted to PV A-fragments with
// quad shuffles — no P smem round trip.
// ---------------------------------------------------------------------------
#define ATM 128
#define AT_STR 68
// Qb[128][68] + 2 stages x (Kb[64][68] + Vs[64][68])
#define ATTN_SMEM_BYTES (384 * AT_STR * 4)   // 104448

__global__ void __launch_bounds__(256, 2)
attn_mma_kernel(const float* __restrict__ qkv, float* __restrict__ out)
{
    extern __shared__ float sm[];
    float* Qb = sm;                   // [row][d]
    float* KV = Qb + ATM * AT_STR;    // stage s: K at s*2*64*68, V at +64*68

    const int tid  = threadIdx.x;
    const int lane = tid & 31;
    const int warp = tid >> 5;        // 0..7
    const int g    = lane >> 2;       // 0..7
    const int t    = lane & 3;        // 0..3
    const int m0   = warp * 16;
    const int qt   = gridDim.x - 1 - blockIdx.x;   // big tiles first
    const int h    = blockIdx.y;
    const int b    = blockIdx.z;

    // Q tile load (pre-scaled + pre-rounded by GEMM epilogue)
    const float* qbase = qkv + (size_t)(b * T_ + qt * ATM) * E3 + h * DH_;
    #pragma unroll
    for (int i = 0; i < 8; ++i) {
        int c = tid + i * 256;
        int row = c >> 4, c4 = (c & 15) << 2;
        cp_async16(&Qb[row * AT_STR + c4], qbase + (size_t)row * E3 + c4);
    }
    cp_commit();

    const int nTiles = 2 * qt + 2;

    auto issueKV = [&](int n, int s) {
        const float* kbase = qkv + (size_t)(b * T_ + n * 64) * E3 + D_ + h * DH_;
        float* Kb = KV + s * 2 * 64 * AT_STR;
        float* Vb = Kb + 64 * AT_STR;
        #pragma unroll
        for (int i = 0; i < 4; ++i) {
            int c = tid + i * 256;
            int row = c >> 4, c4 = (c & 15) << 2;
            const float* kp = kbase + (size_t)row * E3 + c4;
            cp_async16(&Kb[row * AT_STR + c4], kp);
            cp_async16(&Vb[row * AT_STR + c4], kp + D_);
        }
        cp_commit();
    };

    issueKV(0, 0);
    issueKV(1, 1);

    float pacc[8][4] = {};
    float m0r = -3.0e38f, m1r = -3.0e38f;
    float l0 = 0.0f, l1 = 0.0f;

    const int src0 = (lane & 28) | (t >> 1);   // quad-shuffle source lanes
    const bool odd = (t & 1);

    for (int n = 0; n < nTiles; ++n) {
        const int s = n & 1;
        if (n + 1 < nTiles) cp_wait<1>();
        else                cp_wait<0>();
        __syncthreads();

        const float* Kb = KV + s * 2 * 64 * AT_STR;
        const float* Vb = Kb + 64 * AT_STR;

        // S = Q @ K^T   (rows m0..m0+15)
        float sacc[8][4] = {};
        #pragma unroll
        for (int ks = 0; ks < 64; ks += 8) {
            float ab[4];
            int aoff = (m0 + g) * AT_STR + ks + t;
            ab[0] = Qb[aoff];     ab[1] = Qb[aoff + 8 * AT_STR];
            ab[2] = Qb[aoff + 4]; ab[3] = Qb[aoff + 8 * AT_STR + 4];
            #pragma unroll
            for (int j = 0; j < 8; ++j) {
                int boff = (j * 8 + g) * AT_STR + ks + t;
                mma_tf32(sacc[j], ab, Kb[boff], Kb[boff + 4]);
            }
        }

        // Causal mask on tiles crossing the diagonal (global indices)
        if (n >= 2 * qt) {
            int rg0 = qt * ATM + m0 + g;
            int rg1 = rg0 + 8;
            #pragma unroll
            for (int j = 0; j < 8; ++j) {
                int c0 = n * 64 + j * 8 + 2 * t, c1 = c0 + 1;
                if (c0 > rg0) sacc[j][0] = -3.0e38f;
                if (c1 > rg0) sacc[j][1] = -3.0e38f;
                if (c0 > rg1) sacc[j][2] = -3.0e38f;
                if (c1 > rg1) sacc[j][3] = -3.0e38f;
            }
        }

        // Online softmax in base-2 units (register frags, quad shuffles)
        float mx0 = -3.0e38f, mx1 = -3.0e38f;
        #pragma unroll
        for (int j = 0; j < 8; ++j) {
            mx0 = fmaxf(mx0, fmaxf(sacc[j][0], sacc[j][1]));
            mx1 = fmaxf(mx1, fmaxf(sacc[j][2], sacc[j][3]));
        }
        mx0 = fmaxf(mx0, __shfl_xor_sync(0xffffffffu, mx0, 1));
        mx0 = fmaxf(mx0, __shfl_xor_sync(0xffffffffu, mx0, 2));
        mx1 = fmaxf(mx1, __shfl_xor_sync(0xffffffffu, mx1, 1));
        mx1 = fmaxf(mx1, __shfl_xor_sync(0xffffffffu, mx1, 2));

        float mn0 = fmaxf(m0r, mx0);
        float mn1 = fmaxf(m1r, mx1);
        float cr0 = ex2f(m0r - mn0);
        float cr1 = ex2f(m1r - mn1);
        m0r = mn0; m1r = mn1;

        float rs0 = 0.0f, rs1 = 0.0f;
        #pragma unroll
        for (int j = 0; j < 8; ++j) {
            float p0 = ex2f(sacc[j][0] - mn0);
            float p1 = ex2f(sacc[j][1] - mn0);
            float p2 = ex2f(sacc[j][2] - mn1);
            float p3 = ex2f(sacc[j][3] - mn1);
            rs0 += p0 + p1; rs1 += p2 + p3;
            sacc[j][0] = tf32r(p0); sacc[j][1] = tf32r(p1);
            sacc[j][2] = tf32r(p2); sacc[j][3] = tf32r(p3);
        }
        rs0 += __shfl_xor_sync(0xffffffffu, rs0, 1);
        rs0 += __shfl_xor_sync(0xffffffffu, rs0, 2);
        rs1 += __shfl_xor_sync(0xffffffffu, rs1, 1);
        rs1 += __shfl_xor_sync(0xffffffffu, rs1, 2);
        l0 = l0 * cr0 + rs0;
        l1 = l1 * cr1 + rs1;

        #pragma unroll
        for (int j = 0; j < 8; ++j) {
            pacc[j][0] *= cr0; pacc[j][1] *= cr0;
            pacc[j][2] *= cr1; pacc[j][3] *= cr1;
        }

        // O += P @ V : permute S accumulator frag -> PV A-frag via quad shuffles
        #pragma unroll
        for (int jj = 0; jj < 8; ++jj) {
            float q0 = __shfl_sync(0xffffffffu, sacc[jj][0], src0);
            float q1 = __shfl_sync(0xffffffffu, sacc[jj][1], src0);
            float q2 = __shfl_sync(0xffffffffu, sacc[jj][2], src0);
            float q3 = __shfl_sync(0xffffffffu, sacc[jj][3], src0);
            float r0 = __shfl_sync(0xffffffffu, sacc[jj][0], src0 + 2);
            float r1 = __shfl_sync(0xffffffffu, sacc[jj][1], src0 + 2);
            float r2 = __shfl_sync(0xffffffffu, sacc[jj][2], src0 + 2);
            float r3 = __shfl_sync(0xffffffffu, sacc[jj][3], src0 + 2);
            float pf[4];
            pf[0] = odd ? q1 : q0;   // P[g][8jj + t]
            pf[1] = odd ? q3 : q2;   // P[g+8][8jj + t]
            pf[2] = odd ? r1 : r0;   // P[g][8jj + t + 4]
            pf[3] = odd ? r3 : r2;   // P[g+8][8jj + t + 4]
            const int ks = jj * 8;
            #pragma unroll
            for (int j = 0; j < 8; ++j) {
                float b0 = Vb[(ks + t) * AT_STR + j * 8 + g];
                float b1 = Vb[(ks + t + 4) * AT_STR + j * 8 + g];
                mma_tf32(pacc[j], pf, b0, b1);
            }
        }

        __syncthreads();   // all warps done reading stage s
        if (n + 2 < nTiles) issueKV(n + 2, s);
    }

    // Epilogue: normalize, rna-round (proj GEMM consumes raw), store
    float linv0 = 1.0f / l0, linv1 = 1.0f / l1;
    float* obase = out + (size_t)(b * T_ + qt * ATM) * D_ + h * DH_;
    #pragma unroll
    for (int j = 0; j < 8; ++j) {
        *(float2*)(obase + (size_t)(m0 + g) * D_ + j * 8 + 2 * t) =
            make_float2(tf32r(pacc[j][0] * linv0), tf32r(pacc[j][1] * linv0));
        *(float2*)(obase + (size_t)(m0 + g + 8) * D_ + j * 8 + 2 * t) =
            make_float2(tf32r(pacc[j][2] * linv1), tf32r(pacc[j][3] * linv1));
    }
}

// ---------------------------------------------------------------------------
extern "C" void kernel_launch(void* const* d_in, const int* in_sizes, int n_in,
                              void* d_out, int out_size)
{
    const float* x      = (const float*)d_in[0];
    const float* w_attn = (const float*)d_in[1];
    const float* w_proj = (const float*)d_in[2];
    float* out = (float*)d_out;

    float *qkv, *att, *xr, *war, *wpr;
    cudaGetSymbolAddress((void**)&qkv, g_qkv);
    cudaGetSymbolAddress((void**)&att, g_att);
    cudaGetSymbolAddress((void**)&xr,  g_xr);
    cudaGetSymbolAddress((void**)&war, g_war);
    cudaGetSymbolAddress((void**)&wpr, g_wpr);

    cudaFuncSetAttribute(gemm_nt_tf32,
                         cudaFuncAttributeMaxDynamicSharedMemorySize, GEMM_SMEM_BYTES);
    cudaFuncSetAttribute(attn_mma_kernel,
                         cudaFuncAttributeMaxDynamicSharedMemorySize, ATTN_SMEM_BYTES);

    // 0) Pre-round inputs to tf32 (rna) so GEMMs can cp.async raw
    {
        int n4x = NTOK * D_ / 4, n4a = E3 * D_ / 4, n4p = D_ * D_ / 4;
        round_tf32_kernel<<<(n4x + 255) / 256, 256>>>((const float4*)x, (float4*)xr, n4x);
        round_tf32_kernel<<<(n4a + 255) / 256, 256>>>((const float4*)w_attn, (float4*)war, n4a);
        round_tf32_kernel<<<(n4p + 255) / 256, 256>>>((const float4*)w_proj, (float4*)wpr, n4p);
    }

    // 1) QKV projection (epilogue rounds; Q columns pre-scaled by 0.125*log2e)
    {
        dim3 grid(E3 / BN, NTOK / BM);
        gemm_nt_tf32<<<grid, 256, GEMM_SMEM_BYTES>>>(xr, war, qkv, NTOK, E3, D_, 1);
    }

    // 2) Causal flash attention (tensor cores, double-buffered cp.async)
    {
        dim3 grid(T_ / ATM, H_, B_);
        attn_mma_kernel<<<grid, 256, ATTN_SMEM_BYTES>>>(qkv, att);
    }

    // 3) Output projection (plain f32 epilogue — final output)
    {
        dim3 grid(D_ / BN, NTOK / BM);
        gemm_nt_tf32<<<grid, 256, GEMM_SMEM_BYTES>>>(att, wpr, out, NTOK, D_, D_, 0);
    }
}

// round 12
// speedup vs baseline: 1.2401x; 1.0522x over previous
#include <cuda_runtime.h>
#include <math.h>
#include <stdint.h>

// Problem constants
#define B_   4
#define T_   2048
#define D_   1024
#define H_   16
#define DH_  64
#define NTOK (B_ * T_)     // 8192
#define E3   (3 * D_)      // 3072

// softmax scale folded with log2(e): logits come out in base-2 units
#define QSCALE 0.18033688011112042f   // 0.125 * log2(e)

// Scratch (device globals: allocation-free rule)
__device__ __align__(16) float g_qkv[NTOK * E3];   // [8192, 3072] (pre-rounded, Q pre-scaled)
__device__ __align__(16) float g_att[NTOK * D_];   // [8192, 1024] (pre-rounded)
__device__ __align__(16) float g_xr [NTOK * D_];   // tf32-rounded x
__device__ __align__(16) float g_war[E3 * D_];     // tf32-rounded w_attn
__device__ __align__(16) float g_wpr[D_ * D_];     // tf32-rounded w_proj

// ---------------------------------------------------------------------------
// Helpers
// ---------------------------------------------------------------------------
__device__ __forceinline__ float tf32r(float x) {
    uint32_t u;
    asm("cvt.rna.tf32.f32 %0, %1;" : "=r"(u) : "f"(x));
    return __uint_as_float(u);
}

__device__ __forceinline__ float ex2f(float x) {
    float r;
    asm("ex2.approx.ftz.f32 %0, %1;" : "=f"(r) : "f"(x));
    return r;
}

__device__ __forceinline__ void mma_tf32(float* c, const float* a, float b0, float b1) {
    asm volatile(
        "mma.sync.aligned.m16n8k8.row.col.f32.tf32.tf32.f32 "
        "{%0,%1,%2,%3}, {%4,%5,%6,%7}, {%8,%9}, {%0,%1,%2,%3};\n"
        : "+f"(c[0]), "+f"(c[1]), "+f"(c[2]), "+f"(c[3])
        : "r"(__float_as_uint(a[0])), "r"(__float_as_uint(a[1])),
          "r"(__float_as_uint(a[2])), "r"(__float_as_uint(a[3])),
          "r"(__float_as_uint(b0)), "r"(__float_as_uint(b1)));
}

__device__ __forceinline__ void mma_tf32u(float* c, const uint32_t* a,
                                          uint32_t b0, uint32_t b1) {
    asm volatile(
        "mma.sync.aligned.m16n8k8.row.col.f32.tf32.tf32.f32 "
        "{%0,%1,%2,%3}, {%4,%5,%6,%7}, {%8,%9}, {%0,%1,%2,%3};\n"
        : "+f"(c[0]), "+f"(c[1]), "+f"(c[2]), "+f"(c[3])
        : "r"(a[0]), "r"(a[1]), "r"(a[2]), "r"(a[3]), "r"(b0), "r"(b1));
}

// ldmatrix.x4: four 8x8 b16 matrices == four 8x4 tf32 tiles; thread n gets
// tf32 element (n>>2, n&3) of each tile -> exact mma fragment mapping.
__device__ __forceinline__ void ldsm_x4(uint32_t* r, const float* p) {
    uint32_t a = (uint32_t)__cvta_generic_to_shared(p);
    asm volatile("ldmatrix.sync.aligned.m8n8.x4.shared.b16 {%0,%1,%2,%3}, [%4];"
                 : "=r"(r[0]), "=r"(r[1]), "=r"(r[2]), "=r"(r[3]) : "r"(a));
}

__device__ __forceinline__ void cp_async16(void* smem_dst, const void* gsrc) {
    uint32_t s = (uint32_t)__cvta_generic_to_shared(smem_dst);
    asm volatile("cp.async.cg.shared.global [%0], [%1], 16;\n" :: "r"(s), "l"(gsrc) : "memory");
}
__device__ __forceinline__ void cp_commit() {
    asm volatile("cp.async.commit_group;\n" ::: "memory");
}
template<int N>
__device__ __forceinline__ void cp_wait() {
    asm volatile("cp.async.wait_group %0;\n" :: "n"(N) : "memory");
}

// ---------------------------------------------------------------------------
// Pre-round to tf32 (rna), elementwise
// ---------------------------------------------------------------------------
__global__ void round_tf32_kernel(const float4* __restrict__ in,
                                  float4* __restrict__ out, int n4)
{
    int i = blockIdx.x * blockDim.x + threadIdx.x;
    if (i < n4) {
        float4 v = in[i];
        v.x = tf32r(v.x); v.y = tf32r(v.y); v.z = tf32r(v.z); v.w = tf32r(v.w);
        out[i] = v;
    }
}

// ---------------------------------------------------------------------------
// TF32 NT GEMM, inputs pre-rounded. BM=BN=128, BK=32, 2-stage cp.async
// double buffer, LDSM fragment loads. 256 threads (8 warps), warp 64x32.
// ---------------------------------------------------------------------------
#define BM 128
#define BN 128
#define BK 32
#define TSTR 36                                   // 32 + 4 pad words
#define GEMM_STAGE_WORDS (BM * TSTR)              // 4608 words per tile
#define GEMM_SMEM_BYTES (2 * 2 * GEMM_STAGE_WORDS * 4)   // 73728

__global__ void __launch_bounds__(256, 2)
gemm_nt_tf32(const float* __restrict__ A, const float* __restrict__ Bm,
             float* __restrict__ C, int M, int N, int K, int qkv_mode)
{
    extern __shared__ float smg[];
    const int SW = GEMM_STAGE_WORDS;

    const int tid  = threadIdx.x;
    const int lane = tid & 31;
    const int warp = tid >> 5;
    const int wm   = (warp >> 2) * 64;
    const int wn   = (warp & 3) * 32;
    const int m0   = blockIdx.y * BM;
    const int n0   = blockIdx.x * BN;

    // LDSM per-thread source pattern
    const int l8      = lane & 7;
    const int aRowOff = ((lane >> 3) & 1) * 8;   // matrices 1,3: +8 rows
    const int aColOff = (lane >> 4) * 4;         // matrices 2,3: +4 k
    const int bRowOff = ((lane >> 4) & 1) * 8;   // matrices 2,3: next nj tile
    const int bColOff = ((lane >> 3) & 1) * 4;   // matrices 1,3: +4 k

    float acc[4][4][4] = {};

    const int nIter = K / BK;

    auto issue = [&](int it, int s) {
        float* As = smg + s * 2 * SW;
        float* Bs = As + SW;
        int k0 = it * BK;
        #pragma unroll
        for (int i = 0; i < 4; ++i) {
            int c   = tid + i * 256;
            int row = c >> 3;
            int lk  = (c & 7) << 2;
            cp_async16(&As[row * TSTR + lk], &A[(size_t)(m0 + row) * K + k0 + lk]);
            cp_async16(&Bs[row * TSTR + lk], &Bm[(size_t)(n0 + row) * K + k0 + lk]);
        }
        cp_commit();
    };

    issue(0, 0);
    issue(1, 1);

    for (int it = 0; it < nIter; ++it) {
        int s = it & 1;
        cp_wait<1>();
        __syncthreads();

        const float* As = smg + s * 2 * SW;
        const float* Bs = As + SW;

        #pragma unroll
        for (int ks = 0; ks < BK; ks += 8) {
            uint32_t af[4][4], bf[2][4];
            #pragma unroll
            for (int mi = 0; mi < 4; ++mi)
                ldsm_x4(af[mi], &As[(wm + mi * 16 + aRowOff + l8) * TSTR + ks + aColOff]);
            #pragma unroll
            for (int p = 0; p < 2; ++p)
                ldsm_x4(bf[p], &Bs[(wn + p * 16 + bRowOff + l8) * TSTR + ks + bColOff]);
            #pragma unroll
            for (int mi = 0; mi < 4; ++mi)
                #pragma unroll
                for (int nj = 0; nj < 4; ++nj)
                    mma_tf32u(acc[mi][nj], af[mi],
                              bf[nj >> 1][(nj & 1) * 2], bf[nj >> 1][(nj & 1) * 2 + 1]);
        }
        __syncthreads();
        if (it + 2 < nIter) issue(it + 2, s);
        else cp_commit();   // keep group accounting uniform
    }

    const bool doRound = (qkv_mode != 0);
    const float esc = (doRound && n0 < D_) ? QSCALE : 1.0f;

    #pragma unroll
    for (int mi = 0; mi < 4; ++mi) {
        int row = m0 + wm + mi * 16 + (lane >> 2);
        #pragma unroll
        for (int nj = 0; nj < 4; ++nj) {
            int col = n0 + wn + nj * 8 + ((lane & 3) << 1);
            float2 v0 = make_float2(acc[mi][nj][0] * esc, acc[mi][nj][1] * esc);
            float2 v1 = make_float2(acc[mi][nj][2] * esc, acc[mi][nj][3] * esc);
            if (doRound) {
                v0.x = tf32r(v0.x); v0.y = tf32r(v0.y);
                v1.x = tf32r(v1.x); v1.y = tf32r(v1.y);
            }
            *(float2*)&C[(size_t)row * N + col]       = v0;
            *(float2*)&C[(size_t)(row + 8) * N + col] = v1;
        }
    }
}

// ---------------------------------------------------------------------------
// Flash attention on tensor cores. BLOCK_M=128 q rows (8 warps x 16 rows),
// key tiles of 64, DH=64, 256 threads. K/V double-buffered via cp.async;
// Q/K fragments via LDSM; P stays in registers (quad-shuffle permutation).
// ---------------------------------------------------------------------------
#define ATM 128
#define AT_STR 68
// Qb[128][68] + 2 stages x (Kb[64][68] + Vs[64][68])
#define ATTN_SMEM_BYTES (384 * AT_STR * 4)   // 104448

__global__ void __launch_bounds__(256, 2)
attn_mma_kernel(const float* __restrict__ qkv, float* __restrict__ out)
{
    extern __shared__ float sm[];
    float* Qb = sm;                   // [row][d]
    float* KV = Qb + ATM * AT_STR;    // stage s: K at s*2*64*68, V at +64*68

    const int tid  = threadIdx.x;
    const int lane = tid & 31;
    const int warp = tid >> 5;        // 0..7
    const int g    = lane >> 2;       // 0..7
    const int t    = lane & 3;        // 0..3
    const int m0   = warp * 16;
    const int qt   = gridDim.x - 1 - blockIdx.x;   // big tiles first
    const int h    = blockIdx.y;
    const int b    = blockIdx.z;

    // LDSM per-thread source pattern
    const int l8      = lane & 7;
    const int aRowOff = ((lane >> 3) & 1) * 8;
    const int aColOff = (lane >> 4) * 4;
    const int bRowOff = ((lane >> 4) & 1) * 8;
    const int bColOff = ((lane >> 3) & 1) * 4;

    // Q tile load (pre-scaled + pre-rounded by GEMM epilogue)
    const float* qbase = qkv + (size_t)(b * T_ + qt * ATM) * E3 + h * DH_;
    #pragma unroll
    for (int i = 0; i < 8; ++i) {
        int c = tid + i * 256;
        int row = c >> 4, c4 = (c & 15) << 2;
        cp_async16(&Qb[row * AT_STR + c4], qbase + (size_t)row * E3 + c4);
    }
    cp_commit();

    const int nTiles = 2 * qt + 2;

    auto issueKV = [&](int n, int s) {
        const float* kbase = qkv + (size_t)(b * T_ + n * 64) * E3 + D_ + h * DH_;
        float* Kb = KV + s * 2 * 64 * AT_STR;
        float* Vb = Kb + 64 * AT_STR;
        #pragma unroll
        for (int i = 0; i < 4; ++i) {
            int c = tid + i * 256;
            int row = c >> 4, c4 = (c & 15) << 2;
            const float* kp = kbase + (size_t)row * E3 + c4;
            cp_async16(&Kb[row * AT_STR + c4], kp);
            cp_async16(&Vb[row * AT_STR + c4], kp + D_);
        }
        cp_commit();
    };

    issueKV(0, 0);
    issueKV(1, 1);

    float pacc[8][4] = {};
    float m0r = -3.0e38f, m1r = -3.0e38f;
    float l0 = 0.0f, l1 = 0.0f;

    const int src0 = (lane & 28) | (t >> 1);   // quad-shuffle source lanes
    const bool odd = (t & 1);

    for (int n = 0; n < nTiles; ++n) {
        const int s = n & 1;
        if (n + 1 < nTiles) cp_wait<1>();
        else                cp_wait<0>();
        __syncthreads();

        const float* Kb = KV + s * 2 * 64 * AT_STR;
        const float* Vb = Kb + 64 * AT_STR;

        // S = Q @ K^T   (rows m0..m0+15), LDSM fragment loads
        float sacc[8][4] = {};
        #pragma unroll
        for (int ks = 0; ks < 64; ks += 8) {
            uint32_t aq[4], kb[4][4];
            ldsm_x4(aq, &Qb[(m0 + aRowOff + l8) * AT_STR + ks + aColOff]);
            #pragma unroll
            for (int p = 0; p < 4; ++p)
                ldsm_x4(kb[p], &Kb[(p * 16 + bRowOff + l8) * AT_STR + ks + bColOff]);
            #pragma unroll
            for (int j = 0; j < 8; ++j)
                mma_tf32u(sacc[j], aq,
                          kb[j >> 1][(j & 1) * 2], kb[j >> 1][(j & 1) * 2 + 1]);
        }

        // Causal mask on tiles crossing the diagonal (global indices)
        if (n >= 2 * qt) {
            int rg0 = qt * ATM + m0 + g;
            int rg1 = rg0 + 8;
            #pragma unroll
            for (int j = 0; j < 8; ++j) {
                int c0 = n * 64 + j * 8 + 2 * t, c1 = c0 + 1;
                if (c0 > rg0) sacc[j][0] = -3.0e38f;
                if (c1 > rg0) sacc[j][1] = -3.0e38f;
                if (c0 > rg1) sacc[j][2] = -3.0e38f;
                if (c1 > rg1) sacc[j][3] = -3.0e38f;
            }
        }

        // Online softmax in base-2 units (register frags, quad shuffles)
        float mx0 = -3.0e38f, mx1 = -3.0e38f;
        #pragma unroll
        for (int j = 0; j < 8; ++j) {
            mx0 = fmaxf(mx0, fmaxf(sacc[j][0], sacc[j][1]));
            mx1 = fmaxf(mx1, fmaxf(sacc[j][2], sacc[j][3]));
        }
        mx0 = fmaxf(mx0, __shfl_xor_sync(0xffffffffu, mx0, 1));
        mx0 = fmaxf(mx0, __shfl_xor_sync(0xffffffffu, mx0, 2));
        mx1 = fmaxf(mx1, __shfl_xor_sync(0xffffffffu, mx1, 1));
        mx1 = fmaxf(mx1, __shfl_xor_sync(0xffffffffu, mx1, 2));

        float mn0 = fmaxf(m0r, mx0);
        float mn1 = fmaxf(m1r, mx1);
        float cr0 = ex2f(m0r - mn0);
        float cr1 = ex2f(m1r - mn1);
        m0r = mn0; m1r = mn1;

        float rs0 = 0.0f, rs1 = 0.0f;
        #pragma unroll
        for (int j = 0; j < 8; ++j) {
            float p0 = ex2f(sacc[j][0] - mn0);
            float p1 = ex2f(sacc[j][1] - mn0);
            float p2 = ex2f(sacc[j][2] - mn1);
            float p3 = ex2f(sacc[j][3] - mn1);
            rs0 += p0 + p1; rs1 += p2 + p3;
            sacc[j][0] = tf32r(p0); sacc[j][1] = tf32r(p1);
            sacc[j][2] = tf32r(p2); sacc[j][3] = tf32r(p3);
        }
        rs0 += __shfl_xor_sync(0xffffffffu, rs0, 1);
        rs0 += __shfl_xor_sync(0xffffffffu, rs0, 2);
        rs1 += __shfl_xor_sync(0xffffffffu, rs1, 1);
        rs1 += __shfl_xor_sync(0xffffffffu, rs1, 2);
        l0 = l0 * cr0 + rs0;
        l1 = l1 * cr1 + rs1;

        #pragma unroll
        for (int j = 0; j < 8; ++j) {
            pacc[j][0] *= cr0; pacc[j][1] *= cr0;
            pacc[j][2] *= cr1; pacc[j][3] *= cr1;
        }

        // O += P @ V : permute S accumulator frag -> PV A-frag via quad shuffles
        #pragma unroll
        for (int jj = 0; jj < 8; ++jj) {
            float q0 = __shfl_sync(0xffffffffu, sacc[jj][0], src0);
            float q1 = __shfl_sync(0xffffffffu, sacc[jj][1], src0);
            float q2 = __shfl_sync(0xffffffffu, sacc[jj][2], src0);
            float q3 = __shfl_sync(0xffffffffu, sacc[jj][3], src0);
            float r0 = __shfl_sync(0xffffffffu, sacc[jj][0], src0 + 2);
            float r1 = __shfl_sync(0xffffffffu, sacc[jj][1], src0 + 2);
            float r2 = __shfl_sync(0xffffffffu, sacc[jj][2], src0 + 2);
            float r3 = __shfl_sync(0xffffffffu, sacc[jj][3], src0 + 2);
            float pf[4];
            pf[0] = odd ? q1 : q0;   // P[g][8jj + t]
            pf[1] = odd ? q3 : q2;   // P[g+8][8jj + t]
            pf[2] = odd ? r1 : r0;   // P[g][8jj + t + 4]
            pf[3] = odd ? r3 : r2;   // P[g+8][8jj + t + 4]
            const int ks = jj * 8;
            #pragma unroll
            for (int j = 0; j < 8; ++j) {
                float b0 = Vb[(ks + t) * AT_STR + j * 8 + g];
                float b1 = Vb[(ks + t + 4) * AT_STR + j * 8 + g];
                mma_tf32(pacc[j], pf, b0, b1);
            }
        }

        __syncthreads();   // all warps done reading stage s
        if (n + 2 < nTiles) issueKV(n + 2, s);
    }

    // Epilogue: normalize, rna-round (proj GEMM consumes raw), store
    float linv0 = 1.0f / l0, linv1 = 1.0f / l1;
    float* obase = out + (size_t)(b * T_ + qt * ATM) * D_ + h * DH_;
    #pragma unroll
    for (int j = 0; j < 8; ++j) {
        *(float2*)(obase + (size_t)(m0 + g) * D_ + j * 8 + 2 * t) =
            make_float2(tf32r(pacc[j][0] * linv0), tf32r(pacc[j][1] * linv0));
        *(float2*)(obase + (size_t)(m0 + g + 8) * D_ + j * 8 + 2 * t) =
            make_float2(tf32r(pacc[j][2] * linv1), tf32r(pacc[j][3] * linv1));
    }
}

// ---------------------------------------------------------------------------
extern "C" void kernel_launch(void* const* d_in, const int* in_sizes, int n_in,
                              void* d_out, int out_size)
{
    const float* x      = (const float*)d_in[0];
    const float* w_attn = (const float*)d_in[1];
    const float* w_proj = (const float*)d_in[2];
    float* out = (float*)d_out;

    float *qkv, *att, *xr, *war, *wpr;
    cudaGetSymbolAddress((void**)&qkv, g_qkv);
    cudaGetSymbolAddress((void**)&att, g_att);
    cudaGetSymbolAddress((void**)&xr,  g_xr);
    cudaGetSymbolAddress((void**)&war, g_war);
    cudaGetSymbolAddress((void**)&wpr, g_wpr);

    cudaFuncSetAttribute(gemm_nt_tf32,
                         cudaFuncAttributeMaxDynamicSharedMemorySize, GEMM_SMEM_BYTES);
    cudaFuncSetAttribute(attn_mma_kernel,
                         cudaFuncAttributeMaxDynamicSharedMemorySize, ATTN_SMEM_BYTES);

    // 0) Pre-round inputs to tf32 (rna) so GEMMs can cp.async raw
    {
        int n4x = NTOK * D_ / 4, n4a = E3 * D_ / 4, n4p = D_ * D_ / 4;
        round_tf32_kernel<<<(n4x + 255) / 256, 256>>>((const float4*)x, (float4*)xr, n4x);
        round_tf32_kernel<<<(n4a + 255) / 256, 256>>>((const float4*)w_attn, (float4*)war, n4a);
        round_tf32_kernel<<<(n4p + 255) / 256, 256>>>((const float4*)w_proj, (float4*)wpr, n4p);
    }

    // 1) QKV projection (epilogue rounds; Q columns pre-scaled by 0.125*log2e)
    {
        dim3 grid(E3 / BN, NTOK / BM);
        gemm_nt_tf32<<<grid, 256, GEMM_SMEM_BYTES>>>(xr, war, qkv, NTOK, E3, D_, 1);
    }

    // 2) Causal flash attention (tensor cores, double-buffered cp.async)
    {
        dim3 grid(T_ / ATM, H_, B_);
        attn_mma_kernel<<<grid, 256, ATTN_SMEM_BYTES>>>(qkv, att);
    }

    // 3) Output projection (plain f32 epilogue — final output)
    {
        dim3 grid(D_ / BN, NTOK / BM);
        gemm_nt_tf32<<<grid, 256, GEMM_SMEM_BYTES>>>(att, wpr, out, NTOK, D_, D_, 0);
    }
}